// round 8
// baseline (speedup 1.0000x reference)
#include <cuda_runtime.h>
#include <cuda_bf16.h>
#include <math.h>

#define BG   64
#define NPG  2048
#define EPG  32768
#define NTOT (BG * NPG)         // 131072
#define EDG  (BG * EPG)         // 2097152
#define K1   1639
#define NT1  (BG * K1)          // 104896 (divisible by 64)
#define K2   1312
#define NT2  (BG * K2)          // 83968
#define DIM  64
#define NCLS 6
#define CAP  64                 // fixed CSR bucket capacity (P(deg>=64) ~ 1e-20)
#define FULLMASK 0xFFFFFFFFu

// ---------------- scratch ----------------------------------------------------
__device__ float g_xw[NTOT * DIM];       // x@W (stage1), gathered-xp@W2 (stage2)
__device__ float g_h[NTOT * DIM];        // conv output (relu'd)
__device__ float g_score[NTOT];
__device__ float g_rdeg[NTOT];           // rsqrt(deg incl self-loop)
__device__ int   g_cnt[NTOT];            // in-degree (excl self-loop)
__device__ int   g_elist[NTOT * CAP];    // fixed-stride CSR: src per dst-slot
__device__ int   g_perm[NT1];
__device__ float g_vals[NT1];
__device__ int   g_newid[NTOT];
__device__ float g_x1[BG * 2 * DIM];
__device__ float g_x2[BG * 2 * DIM];

// ---------------- stage-1 init: cnt=0, newid=-1 ------------------------------
__global__ void init1_kernel(int* __restrict__ cnt, int* __restrict__ newid, int n) {
    int t = blockIdx.x * blockDim.x + threadIdx.x;
    int stride = gridDim.x * blockDim.x;
    for (; t < n; t += stride) { cnt[t] = 0; newid[t] = -1; }
}

// fused count + place, 4 edges/thread via int4 (stage 1: all edges valid)
__global__ void place1_kernel(const int4* __restrict__ src4, const int4* __restrict__ dst4,
                              int* __restrict__ cnt, int* __restrict__ elist, int nedge4) {
    int t = blockIdx.x * blockDim.x + threadIdx.x;
    if (t >= nedge4) return;
    int4 s = src4[t];
    int4 d = dst4[t];
    int slot;
    slot = atomicAdd(&cnt[d.x], 1); elist[d.x * CAP + slot] = s.x;
    slot = atomicAdd(&cnt[d.y], 1); elist[d.y * CAP + slot] = s.y;
    slot = atomicAdd(&cnt[d.z], 1); elist[d.z * CAP + slot] = s.z;
    slot = atomicAdd(&cnt[d.w], 1); elist[d.w * CAP + slot] = s.w;
}

// fused remap + count + place, 4 edges/thread (stage 2)
__global__ void place2_kernel(const int4* __restrict__ src4, const int4* __restrict__ dst4,
                              const int* __restrict__ newid,
                              int* __restrict__ cnt, int* __restrict__ elist, int nedge4) {
    int t = blockIdx.x * blockDim.x + threadIdx.x;
    if (t >= nedge4) return;
    int4 s = src4[t];
    int4 d = dst4[t];
    int s2, d2, slot;
    s2 = newid[s.x]; d2 = newid[d.x];
    if (s2 >= 0 && d2 >= 0) { slot = atomicAdd(&cnt[d2], 1); elist[d2 * CAP + slot] = s2; }
    s2 = newid[s.y]; d2 = newid[d.y];
    if (s2 >= 0 && d2 >= 0) { slot = atomicAdd(&cnt[d2], 1); elist[d2 * CAP + slot] = s2; }
    s2 = newid[s.z]; d2 = newid[d.z];
    if (s2 >= 0 && d2 >= 0) { slot = atomicAdd(&cnt[d2], 1); elist[d2 * CAP + slot] = s2; }
    s2 = newid[s.w]; d2 = newid[d.w];
    if (s2 >= 0 && d2 >= 0) { slot = atomicAdd(&cnt[d2], 1); elist[d2 * CAP + slot] = s2; }
}

// ---------------- GEMM: C[n x 64] = gather(A)[n x 64] @ W[64 x 64] ----------
// 64-row tile; thread = 4 rows x 4 cols. W repacked as Ws[k4][j][4] ->
// conflict-free LDS128; A reads are broadcasts. Fuses the rdeg pass.
// If perm != nullptr, row i of A is A[perm[i]] * vals[i] (fused TopK gather+gate).
__global__ __launch_bounds__(256, 4) void matmul64_kernel(
    const float* __restrict__ A, const float* __restrict__ W,
    const int* __restrict__ perm, const float* __restrict__ vals,
    float* __restrict__ C, int nrows,
    const int* __restrict__ cnt, float* __restrict__ rdeg) {
    __shared__ float Ws[16][64][4];   // [k4][col][k-in-group]
    __shared__ float As[64][64];
    int tid = threadIdx.x;
    // fused rdeg pass (cnt is final here: GEMM launches after place)
    int gi = blockIdx.x * 256 + tid;
    if (gi < nrows) rdeg[gi] = rsqrtf((float)(cnt[gi] + 1));
    // repack W: W[k][j] row-major -> Ws[k>>2][j][k&3]
    for (int i = tid; i < 4096; i += 256) {
        int k = i >> 6, j = i & 63;
        Ws[k >> 2][j][k & 3] = W[i];
    }
    int row0 = blockIdx.x * 64;
    {
        float4* s4 = (float4*)&As[0][0];
        for (int i = tid; i < 1024; i += 256) {
            int grow = row0 + (i >> 4);       // grow < nrows (nrows % 64 == 0)
            int arow = perm ? perm[grow] : grow;
            float sc = perm ? vals[grow] : 1.0f;
            float4 v = ((const float4*)(A + (size_t)arow * 64))[i & 15];
            v.x *= sc; v.y *= sc; v.z *= sc; v.w *= sc;
            s4[i] = v;
        }
    }
    __syncthreads();
    int tx = tid & 15;    // col base
    int ty = tid >> 4;    // rows ty*4 .. ty*4+3
    float acc[4][4] = {};
#pragma unroll
    for (int k4 = 0; k4 < 16; k4++) {
        float4 w[4];
#pragma unroll
        for (int c = 0; c < 4; c++)
            w[c] = *(const float4*)&Ws[k4][tx + 16 * c][0];
#pragma unroll
        for (int r = 0; r < 4; r++) {
            float4 a = *(const float4*)&As[ty * 4 + r][k4 * 4];
#pragma unroll
            for (int c = 0; c < 4; c++)
                acc[r][c] += a.x * w[c].x + a.y * w[c].y + a.z * w[c].z + a.w * w[c].w;
        }
    }
#pragma unroll
    for (int r = 0; r < 4; r++) {
        int row = row0 + ty * 4 + r;
#pragma unroll
        for (int c = 0; c < 4; c++)
            C[(size_t)row * 64 + tx + 16 * c] = acc[r][c];
    }
}

// ---------------- fused CSR-gather conv + epilogue + score -------------------
// One warp per dst node. All 32 lanes batch-prefetch edge indices + rdeg
// (coalesced, breaks the per-edge dependent-load chain); the two half-warps
// then consume alternate edges. The inner loop bound limE is even and
// warp-uniform so BOTH halves run exactly limE/2 iterations -> every
// __shfl_sync is executed by all 32 lanes (fixes the R7 divergence crash).
__global__ __launch_bounds__(256) void conv_kernel(
    const int* __restrict__ cnt, const int* __restrict__ elist,
    const float* __restrict__ rdeg, const float* __restrict__ xw,
    const float* __restrict__ bias, const float* __restrict__ p,
    float* __restrict__ h, float* __restrict__ score, int n) {
    int warp = (blockIdx.x * blockDim.x + threadIdx.x) >> 5;
    int lane = threadIdx.x & 31;
    if (warp >= n) return;
    int li   = lane & 15;
    int half = lane >> 4;
    const float4* xw4 = (const float4*)xw;
    float rd = rdeg[warp];
    int m = cnt[warp];
    const int* el = elist + (size_t)warp * CAP;
    float4 acc = make_float4(0.f, 0.f, 0.f, 0.f);
    for (int base = 0; base < m; base += 32) {
        int s = 0; float r = 0.f;
        if (base + lane < m) {
            s = el[base + lane];
            r = rdeg[s];
        }
        int lim  = min(32, m - base);
        int limE = (lim + 1) & ~1;   // even, warp-uniform trip count
#pragma unroll 4
        for (int k = half; k < limE; k += 2) {
            int   kk = (k < lim) ? k : (lim - 1);       // clamp shfl source
            int   ss = __shfl_sync(FULLMASK, s, kk);
            float nr = __shfl_sync(FULLMASK, r, kk) * rd;
            if (k < lim) {
                float4 v = xw4[(size_t)ss * 16 + li];
                acc.x += nr * v.x; acc.y += nr * v.y;
                acc.z += nr * v.z; acc.w += nr * v.w;
            }
        }
    }
    // combine halves (both halves end up with full sums)
    acc.x += __shfl_xor_sync(FULLMASK, acc.x, 16);
    acc.y += __shfl_xor_sync(FULLMASK, acc.y, 16);
    acc.z += __shfl_xor_sync(FULLMASK, acc.z, 16);
    acc.w += __shfl_xor_sync(FULLMASK, acc.w, 16);
    // self-loop (coef 1/deg = rd^2) + bias + relu
    float4 vs = xw4[(size_t)warp * 16 + li];
    float4 b4 = ((const float4*)bias)[li];
    float inv = rd * rd;
    acc.x = fmaxf(acc.x + vs.x * inv + b4.x, 0.f);
    acc.y = fmaxf(acc.y + vs.y * inv + b4.y, 0.f);
    acc.z = fmaxf(acc.z + vs.z * inv + b4.z, 0.f);
    acc.w = fmaxf(acc.w + vs.w * inv + b4.w, 0.f);
    if (half == 0) ((float4*)h)[(size_t)warp * 16 + li] = acc;
    // pooling score: tanh(h.p/||p||). Both halves duplicate -> warp sums are 2x;
    // the 1/sqrt(2) factor corrects dot/sqrt(pp).
    float4 p4 = ((const float4*)p)[li];
    float dot = acc.x * p4.x + acc.y * p4.y + acc.z * p4.z + acc.w * p4.w;
    float pp  = p4.x * p4.x + p4.y * p4.y + p4.z * p4.z + p4.w * p4.w;
#pragma unroll
    for (int o = 16; o; o >>= 1) {
        dot += __shfl_down_sync(FULLMASK, dot, o);
        pp  += __shfl_down_sync(FULLMASK, pp, o);
    }
    if (lane == 0) score[warp] = tanhf(dot * rsqrtf(pp) * 0.7071067811865476f);
}

// ---------------- per-graph top-k via bitonic sort (1024 threads) ------------
// Also zeroes cnt[b*k + r] for the kept nodes (= stage-2 cnt init).
__global__ __launch_bounds__(1024) void topk_kernel(
    const float* __restrict__ score, int n_per, int k,
    int* __restrict__ perm, float* __restrict__ vals, int* __restrict__ newid,
    int* __restrict__ cnt_zero) {
    __shared__ unsigned long long keys[2048];
    int b = blockIdx.x;
    int tid = threadIdx.x;
    const float* sc = score + (size_t)b * n_per;
#pragma unroll
    for (int i = tid; i < 2048; i += 1024) {
        unsigned long long key;
        if (i < n_per) {
            unsigned u = __float_as_uint(sc[i]);
            u = (u & 0x80000000u) ? ~u : (u | 0x80000000u);
            key = ((unsigned long long)(~u) << 32) | (unsigned)i;
        } else {
            key = 0xFFFFFFFFFFFFFFFFull;
        }
        keys[i] = key;
    }
    __syncthreads();
    for (int kk = 2; kk <= 2048; kk <<= 1) {
        for (int jj = kk >> 1; jj > 0; jj >>= 1) {
#pragma unroll
            for (int i = tid; i < 2048; i += 1024) {
                int ixj = i ^ jj;
                if (ixj > i) {
                    unsigned long long a = keys[i], c = keys[ixj];
                    bool swap = ((i & kk) == 0) ? (a > c) : (a < c);
                    if (swap) { keys[i] = c; keys[ixj] = a; }
                }
            }
            __syncthreads();
        }
    }
    for (int r = tid; r < k; r += 1024) {
        int idx = (int)(keys[r] & 0xFFFFFFFFull);
        int g_old = b * n_per + idx;
        perm[b * k + r] = g_old;
        vals[b * k + r] = sc[idx];
        if (newid) newid[g_old] = b * k + r;
        if (cnt_zero) cnt_zero[b * k + r] = 0;
    }
}

// ---------------- per-graph [max | mean] over gathered+gated rows ------------
__global__ __launch_bounds__(1024) void maxmean_kernel(
    const float* __restrict__ h, const int* __restrict__ perm,
    const float* __restrict__ vals, int k, float* __restrict__ out) {
    __shared__ float smx[1024], ssm[1024];
    int b = blockIdx.x;
    int tid = threadIdx.x;
    int j = tid & 63;
    int rg = tid >> 6;          // 0..15
    float mx = -INFINITY, sum = 0.f;
    for (int r = rg; r < k; r += 16) {
        int idx = perm[b * k + r];
        float v = h[(size_t)idx * 64 + j] * vals[b * k + r];
        mx = fmaxf(mx, v);
        sum += v;
    }
    smx[tid] = mx;
    ssm[tid] = sum;
    __syncthreads();
    for (int s = 8; s >= 1; s >>= 1) {
        if (rg < s) {
            smx[rg * 64 + j] = fmaxf(smx[rg * 64 + j], smx[(rg + s) * 64 + j]);
            ssm[rg * 64 + j] += ssm[(rg + s) * 64 + j];
        }
        __syncthreads();
    }
    if (rg == 0) {
        out[b * 128 + j]      = smx[j];
        out[b * 128 + 64 + j] = ssm[j] / (float)k;
    }
}

// ---------------- MLP head ---------------------------------------------------
__global__ __launch_bounds__(64) void head_kernel(
    const float* __restrict__ x1, const float* __restrict__ x2,
    const float* __restrict__ l1w, const float* __restrict__ l1b,
    const float* __restrict__ l2w, const float* __restrict__ l2b,
    float* __restrict__ out) {
    int b = blockIdx.x;
    int j = threadIdx.x;
    __shared__ float hv[128];
    __shared__ float h1[64];
    hv[j]      = x1[b * 128 + j]      + x2[b * 128 + j];
    hv[j + 64] = x1[b * 128 + 64 + j] + x2[b * 128 + 64 + j];
    __syncthreads();
    float acc = l1b[j];
#pragma unroll 8
    for (int k = 0; k < 128; k++) acc += hv[k] * l1w[k * 64 + j];
    h1[j] = fmaxf(acc, 0.f);
    __syncthreads();
    if (j < NCLS) {
        float o = l2b[j];
#pragma unroll 8
        for (int kk = 0; kk < 64; kk++) o += h1[kk] * l2w[kk * NCLS + j];
        out[b * NCLS + j] = o;
    }
}

// ---------------- host orchestration ----------------------------------------
extern "C" void kernel_launch(void* const* d_in, const int* in_sizes, int n_in,
                              void* d_out, int out_size) {
    const float* x   = (const float*)d_in[0];
    const int* ei    = (const int*)d_in[1];
    const float* W1  = (const float*)d_in[3];
    const float* b1  = (const float*)d_in[4];
    const float* p1  = (const float*)d_in[5];
    const float* W2  = (const float*)d_in[6];
    const float* b2  = (const float*)d_in[7];
    const float* p2  = (const float*)d_in[8];
    const float* l1w = (const float*)d_in[9];
    const float* l1b = (const float*)d_in[10];
    const float* l2w = (const float*)d_in[11];
    const float* l2b = (const float*)d_in[12];
    float* out = (float*)d_out;

    const int4* src4 = (const int4*)ei;
    const int4* dst4 = (const int4*)(ei + EDG);

    float *xw, *h, *score, *rdeg, *vals, *x1, *x2;
    int *cnt, *elist, *perm, *newid;
    cudaGetSymbolAddress((void**)&xw,     g_xw);
    cudaGetSymbolAddress((void**)&h,      g_h);
    cudaGetSymbolAddress((void**)&score,  g_score);
    cudaGetSymbolAddress((void**)&rdeg,   g_rdeg);
    cudaGetSymbolAddress((void**)&cnt,    g_cnt);
    cudaGetSymbolAddress((void**)&elist,  g_elist);
    cudaGetSymbolAddress((void**)&perm,   g_perm);
    cudaGetSymbolAddress((void**)&newid,  g_newid);
    cudaGetSymbolAddress((void**)&vals,   g_vals);
    cudaGetSymbolAddress((void**)&x1,     g_x1);
    cudaGetSymbolAddress((void**)&x2,     g_x2);

    const int TB = 256;
    const int E4 = EDG / 4;
    const int EB4 = (E4 + TB - 1) / TB;

    // ===================== Stage 1 =====================
    init1_kernel<<<256, TB>>>(cnt, newid, NTOT);
    place1_kernel<<<EB4, TB>>>(src4, dst4, cnt, elist, E4);

    matmul64_kernel<<<NTOT / 64, TB>>>(x, W1, nullptr, nullptr, xw, NTOT, cnt, rdeg);
    conv_kernel<<<(NTOT * 32 + TB - 1) / TB, TB>>>(cnt, elist, rdeg, xw, b1, p1, h, score, NTOT);

    topk_kernel<<<BG, 1024>>>(score, NPG, K1, perm, vals, newid, cnt);  // zeroes cnt for stage 2
    maxmean_kernel<<<BG, 1024>>>(h, perm, vals, K1, x1);

    // ===================== Stage 2 =====================
    place2_kernel<<<EB4, TB>>>(src4, dst4, newid, cnt, elist, E4);

    matmul64_kernel<<<NT1 / 64, TB>>>(h, W2, perm, vals, xw, NT1, cnt, rdeg);
    conv_kernel<<<(NT1 * 32 + TB - 1) / TB, TB>>>(cnt, elist, rdeg, xw, b2, p2, h, score, NT1);

    topk_kernel<<<BG, 1024>>>(score, K1, K2, perm, vals, (int*)nullptr, (int*)nullptr);
    maxmean_kernel<<<BG, 1024>>>(h, perm, vals, K2, x2);

    // ===================== Head =====================
    head_kernel<<<BG, 64>>>(x1, x2, l1w, l1b, l2w, l2b, out);
}

// round 9
// speedup vs baseline: 1.1054x; 1.1054x over previous
#include <cuda_runtime.h>
#include <cuda_bf16.h>
#include <math.h>

#define BG   64
#define NPG  2048
#define EPG  32768
#define NTOT (BG * NPG)         // 131072
#define EDG  (BG * EPG)         // 2097152
#define K1   1639
#define NT1  (BG * K1)          // 104896 (divisible by 64)
#define K2   1312
#define NT2  (BG * K2)          // 83968
#define DIM  64
#define NCLS 6
#define CAP  64                 // fixed CSR bucket capacity (P(deg>=64) ~ 1e-20)
#define FULLMASK 0xFFFFFFFFu

// ---------------- scratch ----------------------------------------------------
__device__ float g_xw[NTOT * DIM];       // (A@W)*rdeg  (pre-scaled rows)
__device__ float g_h[NTOT * DIM];        // conv output (relu'd)
__device__ float g_score[NTOT];
__device__ float g_rdeg[NTOT];           // rsqrt(deg incl self-loop)
__device__ int   g_cnt[NTOT];            // in-degree (excl self-loop)
__device__ int   g_elist[NTOT * CAP];    // fixed-stride CSR: src per dst-slot
__device__ int   g_perm[NT1];
__device__ float g_vals[NT1];
__device__ int   g_newid[NTOT];
__device__ float g_x1[BG * 2 * DIM];
__device__ float g_x2[BG * 2 * DIM];

// ---------------- stage-1 init: cnt=0, newid=-1 ------------------------------
__global__ void init1_kernel(int* __restrict__ cnt, int* __restrict__ newid, int n) {
    int t = blockIdx.x * blockDim.x + threadIdx.x;
    int stride = gridDim.x * blockDim.x;
    for (; t < n; t += stride) { cnt[t] = 0; newid[t] = -1; }
}

// fused count + place, 4 edges/thread via int4 (stage 1: all edges valid)
__global__ void place1_kernel(const int4* __restrict__ src4, const int4* __restrict__ dst4,
                              int* __restrict__ cnt, int* __restrict__ elist, int nedge4) {
    int t = blockIdx.x * blockDim.x + threadIdx.x;
    if (t >= nedge4) return;
    int4 s = src4[t];
    int4 d = dst4[t];
    int slot;
    slot = atomicAdd(&cnt[d.x], 1); elist[d.x * CAP + slot] = s.x;
    slot = atomicAdd(&cnt[d.y], 1); elist[d.y * CAP + slot] = s.y;
    slot = atomicAdd(&cnt[d.z], 1); elist[d.z * CAP + slot] = s.z;
    slot = atomicAdd(&cnt[d.w], 1); elist[d.w * CAP + slot] = s.w;
}

// fused remap + count + place, 4 edges/thread (stage 2)
__global__ void place2_kernel(const int4* __restrict__ src4, const int4* __restrict__ dst4,
                              const int* __restrict__ newid,
                              int* __restrict__ cnt, int* __restrict__ elist, int nedge4) {
    int t = blockIdx.x * blockDim.x + threadIdx.x;
    if (t >= nedge4) return;
    int4 s = src4[t];
    int4 d = dst4[t];
    int s2, d2, slot;
    s2 = newid[s.x]; d2 = newid[d.x];
    if (s2 >= 0 && d2 >= 0) { slot = atomicAdd(&cnt[d2], 1); elist[d2 * CAP + slot] = s2; }
    s2 = newid[s.y]; d2 = newid[d.y];
    if (s2 >= 0 && d2 >= 0) { slot = atomicAdd(&cnt[d2], 1); elist[d2 * CAP + slot] = s2; }
    s2 = newid[s.z]; d2 = newid[d.z];
    if (s2 >= 0 && d2 >= 0) { slot = atomicAdd(&cnt[d2], 1); elist[d2 * CAP + slot] = s2; }
    s2 = newid[s.w]; d2 = newid[d.w];
    if (s2 >= 0 && d2 >= 0) { slot = atomicAdd(&cnt[d2], 1); elist[d2 * CAP + slot] = s2; }
}

// ---------------- GEMM: C[n x 64] = rdeg[i] * (gather(A) @ W)[i] -------------
// 64-row tile; thread = 4 rows x 4 cols. W repacked as Ws[k4][j][4] ->
// conflict-free LDS128; A reads are broadcasts. Output rows are PRE-SCALED by
// rdeg[row] = rsqrt(cnt[row]+1) so the conv inner loop needs no per-edge norm.
// Also writes the rdeg[] array (for the conv's dst-side factor).
// If perm != nullptr, row i of A is A[perm[i]] * vals[i] (fused TopK gather+gate).
__global__ __launch_bounds__(256, 4) void matmul64_kernel(
    const float* __restrict__ A, const float* __restrict__ W,
    const int* __restrict__ perm, const float* __restrict__ vals,
    float* __restrict__ C, int nrows,
    const int* __restrict__ cnt, float* __restrict__ rdeg) {
    __shared__ float Ws[16][64][4];   // [k4][col][k-in-group]
    __shared__ float As[64][64];
    int tid = threadIdx.x;
    // rdeg array pass (cnt is final here: GEMM launches after place)
    int gi = blockIdx.x * 256 + tid;
    if (gi < nrows) rdeg[gi] = rsqrtf((float)(cnt[gi] + 1));
    // repack W: W[k][j] row-major -> Ws[k>>2][j][k&3]
    for (int i = tid; i < 4096; i += 256) {
        int k = i >> 6, j = i & 63;
        Ws[k >> 2][j][k & 3] = W[i];
    }
    int row0 = blockIdx.x * 64;
    {
        float4* s4 = (float4*)&As[0][0];
        for (int i = tid; i < 1024; i += 256) {
            int grow = row0 + (i >> 4);       // grow < nrows (nrows % 64 == 0)
            int arow = perm ? perm[grow] : grow;
            float sc = perm ? vals[grow] : 1.0f;
            float4 v = ((const float4*)(A + (size_t)arow * 64))[i & 15];
            v.x *= sc; v.y *= sc; v.z *= sc; v.w *= sc;
            s4[i] = v;
        }
    }
    __syncthreads();
    int tx = tid & 15;    // col base
    int ty = tid >> 4;    // rows ty*4 .. ty*4+3
    float acc[4][4] = {};
#pragma unroll
    for (int k4 = 0; k4 < 16; k4++) {
        float4 w[4];
#pragma unroll
        for (int c = 0; c < 4; c++)
            w[c] = *(const float4*)&Ws[k4][tx + 16 * c][0];
#pragma unroll
        for (int r = 0; r < 4; r++) {
            float4 a = *(const float4*)&As[ty * 4 + r][k4 * 4];
#pragma unroll
            for (int c = 0; c < 4; c++)
                acc[r][c] += a.x * w[c].x + a.y * w[c].y + a.z * w[c].z + a.w * w[c].w;
        }
    }
#pragma unroll
    for (int r = 0; r < 4; r++) {
        int row = row0 + ty * 4 + r;
        float rr = rsqrtf((float)(cnt[row] + 1));
#pragma unroll
        for (int c = 0; c < 4; c++)
            C[(size_t)row * 64 + tx + 16 * c] = acc[r][c] * rr;
    }
}

// ---------------- fused CSR-gather conv + epilogue + score -------------------
// One warp per dst node; half-warps process alternate edges with float4 lanes.
// xw rows are pre-scaled by rdeg[src] -> the inner loop is a PURE ROW SUM
// (1 broadcast LDG + 1 LDG.128 + 4 FADD per edge). Epilogue applies the
// dst-side factor: h = relu(rd*(sum + xw'[dst]) + b).
__global__ __launch_bounds__(256) void conv_kernel(
    const int* __restrict__ cnt, const int* __restrict__ elist,
    const float* __restrict__ rdeg, const float* __restrict__ xw,
    const float* __restrict__ bias, const float* __restrict__ p,
    float* __restrict__ h, float* __restrict__ score, int n) {
    int warp = (blockIdx.x * blockDim.x + threadIdx.x) >> 5;
    int lane = threadIdx.x & 31;
    if (warp >= n) return;
    int li   = lane & 15;
    int half = lane >> 4;
    const float4* xw4 = (const float4*)xw;
    float rd = rdeg[warp];
    int m = cnt[warp];
    const int* el = elist + (size_t)warp * CAP;
    float4 acc = make_float4(0.f, 0.f, 0.f, 0.f);
#pragma unroll 4
    for (int e = half; e < m; e += 2) {
        int s = el[e];
        float4 v = xw4[(size_t)s * 16 + li];
        acc.x += v.x; acc.y += v.y; acc.z += v.z; acc.w += v.w;
    }
    // combine halves (both halves end up with full sums)
    acc.x += __shfl_xor_sync(FULLMASK, acc.x, 16);
    acc.y += __shfl_xor_sync(FULLMASK, acc.y, 16);
    acc.z += __shfl_xor_sync(FULLMASK, acc.z, 16);
    acc.w += __shfl_xor_sync(FULLMASK, acc.w, 16);
    // epilogue: h = relu(rd*(sum + xw'[dst]) + b)
    float4 vs = xw4[(size_t)warp * 16 + li];
    float4 b4 = ((const float4*)bias)[li];
    acc.x = fmaxf((acc.x + vs.x) * rd + b4.x, 0.f);
    acc.y = fmaxf((acc.y + vs.y) * rd + b4.y, 0.f);
    acc.z = fmaxf((acc.z + vs.z) * rd + b4.z, 0.f);
    acc.w = fmaxf((acc.w + vs.w) * rd + b4.w, 0.f);
    if (half == 0) ((float4*)h)[(size_t)warp * 16 + li] = acc;
    // pooling score: tanh(h.p/||p||). Both halves duplicate -> warp sums are 2x;
    // the 1/sqrt(2) factor corrects dot/sqrt(pp).
    float4 p4 = ((const float4*)p)[li];
    float dot = acc.x * p4.x + acc.y * p4.y + acc.z * p4.z + acc.w * p4.w;
    float pp  = p4.x * p4.x + p4.y * p4.y + p4.z * p4.z + p4.w * p4.w;
#pragma unroll
    for (int o = 16; o; o >>= 1) {
        dot += __shfl_down_sync(FULLMASK, dot, o);
        pp  += __shfl_down_sync(FULLMASK, pp, o);
    }
    if (lane == 0) score[warp] = tanhf(dot * rsqrtf(pp) * 0.7071067811865476f);
}

// ---------------- per-graph top-k via bitonic sort (1024 threads) ------------
// Also zeroes cnt[b*k + r] for the kept nodes (= stage-2 cnt init).
__global__ __launch_bounds__(1024) void topk_kernel(
    const float* __restrict__ score, int n_per, int k,
    int* __restrict__ perm, float* __restrict__ vals, int* __restrict__ newid,
    int* __restrict__ cnt_zero) {
    __shared__ unsigned long long keys[2048];
    int b = blockIdx.x;
    int tid = threadIdx.x;
    const float* sc = score + (size_t)b * n_per;
#pragma unroll
    for (int i = tid; i < 2048; i += 1024) {
        unsigned long long key;
        if (i < n_per) {
            unsigned u = __float_as_uint(sc[i]);
            u = (u & 0x80000000u) ? ~u : (u | 0x80000000u);
            key = ((unsigned long long)(~u) << 32) | (unsigned)i;
        } else {
            key = 0xFFFFFFFFFFFFFFFFull;
        }
        keys[i] = key;
    }
    __syncthreads();
    for (int kk = 2; kk <= 2048; kk <<= 1) {
        for (int jj = kk >> 1; jj > 0; jj >>= 1) {
#pragma unroll
            for (int i = tid; i < 2048; i += 1024) {
                int ixj = i ^ jj;
                if (ixj > i) {
                    unsigned long long a = keys[i], c = keys[ixj];
                    bool swap = ((i & kk) == 0) ? (a > c) : (a < c);
                    if (swap) { keys[i] = c; keys[ixj] = a; }
                }
            }
            __syncthreads();
        }
    }
    for (int r = tid; r < k; r += 1024) {
        int idx = (int)(keys[r] & 0xFFFFFFFFull);
        int g_old = b * n_per + idx;
        perm[b * k + r] = g_old;
        vals[b * k + r] = sc[idx];
        if (newid) newid[g_old] = b * k + r;
        if (cnt_zero) cnt_zero[b * k + r] = 0;
    }
}

// ---------------- per-graph [max | mean] over gathered+gated rows ------------
__global__ __launch_bounds__(1024) void maxmean_kernel(
    const float* __restrict__ h, const int* __restrict__ perm,
    const float* __restrict__ vals, int k, float* __restrict__ out) {
    __shared__ float smx[1024], ssm[1024];
    int b = blockIdx.x;
    int tid = threadIdx.x;
    int j = tid & 63;
    int rg = tid >> 6;          // 0..15
    float mx = -INFINITY, sum = 0.f;
    for (int r = rg; r < k; r += 16) {
        int idx = perm[b * k + r];
        float v = h[(size_t)idx * 64 + j] * vals[b * k + r];
        mx = fmaxf(mx, v);
        sum += v;
    }
    smx[tid] = mx;
    ssm[tid] = sum;
    __syncthreads();
    for (int s = 8; s >= 1; s >>= 1) {
        if (rg < s) {
            smx[rg * 64 + j] = fmaxf(smx[rg * 64 + j], smx[(rg + s) * 64 + j]);
            ssm[rg * 64 + j] += ssm[(rg + s) * 64 + j];
        }
        __syncthreads();
    }
    if (rg == 0) {
        out[b * 128 + j]      = smx[j];
        out[b * 128 + 64 + j] = ssm[j] / (float)k;
    }
}

// ---------------- MLP head ---------------------------------------------------
__global__ __launch_bounds__(64) void head_kernel(
    const float* __restrict__ x1, const float* __restrict__ x2,
    const float* __restrict__ l1w, const float* __restrict__ l1b,
    const float* __restrict__ l2w, const float* __restrict__ l2b,
    float* __restrict__ out) {
    int b = blockIdx.x;
    int j = threadIdx.x;
    __shared__ float hv[128];
    __shared__ float h1[64];
    hv[j]      = x1[b * 128 + j]      + x2[b * 128 + j];
    hv[j + 64] = x1[b * 128 + 64 + j] + x2[b * 128 + 64 + j];
    __syncthreads();
    float acc = l1b[j];
#pragma unroll 8
    for (int k = 0; k < 128; k++) acc += hv[k] * l1w[k * 64 + j];
    h1[j] = fmaxf(acc, 0.f);
    __syncthreads();
    if (j < NCLS) {
        float o = l2b[j];
#pragma unroll 8
        for (int kk = 0; kk < 64; kk++) o += h1[kk] * l2w[kk * NCLS + j];
        out[b * NCLS + j] = o;
    }
}

// ---------------- host orchestration ----------------------------------------
extern "C" void kernel_launch(void* const* d_in, const int* in_sizes, int n_in,
                              void* d_out, int out_size) {
    const float* x   = (const float*)d_in[0];
    const int* ei    = (const int*)d_in[1];
    const float* W1  = (const float*)d_in[3];
    const float* b1  = (const float*)d_in[4];
    const float* p1  = (const float*)d_in[5];
    const float* W2  = (const float*)d_in[6];
    const float* b2  = (const float*)d_in[7];
    const float* p2  = (const float*)d_in[8];
    const float* l1w = (const float*)d_in[9];
    const float* l1b = (const float*)d_in[10];
    const float* l2w = (const float*)d_in[11];
    const float* l2b = (const float*)d_in[12];
    float* out = (float*)d_out;

    const int4* src4 = (const int4*)ei;
    const int4* dst4 = (const int4*)(ei + EDG);

    float *xw, *h, *score, *rdeg, *vals, *x1, *x2;
    int *cnt, *elist, *perm, *newid;
    cudaGetSymbolAddress((void**)&xw,     g_xw);
    cudaGetSymbolAddress((void**)&h,      g_h);
    cudaGetSymbolAddress((void**)&score,  g_score);
    cudaGetSymbolAddress((void**)&rdeg,   g_rdeg);
    cudaGetSymbolAddress((void**)&cnt,    g_cnt);
    cudaGetSymbolAddress((void**)&elist,  g_elist);
    cudaGetSymbolAddress((void**)&perm,   g_perm);
    cudaGetSymbolAddress((void**)&newid,  g_newid);
    cudaGetSymbolAddress((void**)&vals,   g_vals);
    cudaGetSymbolAddress((void**)&x1,     g_x1);
    cudaGetSymbolAddress((void**)&x2,     g_x2);

    const int TB = 256;
    const int E4 = EDG / 4;
    const int EB4 = (E4 + TB - 1) / TB;

    // ===================== Stage 1 =====================
    init1_kernel<<<256, TB>>>(cnt, newid, NTOT);
    place1_kernel<<<EB4, TB>>>(src4, dst4, cnt, elist, E4);

    matmul64_kernel<<<NTOT / 64, TB>>>(x, W1, nullptr, nullptr, xw, NTOT, cnt, rdeg);
    conv_kernel<<<(NTOT * 32 + TB - 1) / TB, TB>>>(cnt, elist, rdeg, xw, b1, p1, h, score, NTOT);

    topk_kernel<<<BG, 1024>>>(score, NPG, K1, perm, vals, newid, cnt);  // zeroes cnt for stage 2
    maxmean_kernel<<<BG, 1024>>>(h, perm, vals, K1, x1);

    // ===================== Stage 2 =====================
    place2_kernel<<<EB4, TB>>>(src4, dst4, newid, cnt, elist, E4);

    matmul64_kernel<<<NT1 / 64, TB>>>(h, W2, perm, vals, xw, NT1, cnt, rdeg);
    conv_kernel<<<(NT1 * 32 + TB - 1) / TB, TB>>>(cnt, elist, rdeg, xw, b2, p2, h, score, NT1);

    topk_kernel<<<BG, 1024>>>(score, K1, K2, perm, vals, (int*)nullptr, (int*)nullptr);
    maxmean_kernel<<<BG, 1024>>>(h, perm, vals, K2, x2);

    // ===================== Head =====================
    head_kernel<<<BG, 64>>>(x1, x2, l1w, l1b, l2w, l2b, out);
}